// round 13
// baseline (speedup 1.0000x reference)
#include <cuda_runtime.h>

// Fixed problem shape
#define HH   50
#define GG   200
#define TT   2048
#define BB   8192
#define BPB  64          // batches per block
#define NW   12          // warps: 0-7 own 3 pairs, 8-11 own 2 pairs (8*6+4*4=64)
#define NTHR 384
#define XROW 66

typedef unsigned long long ull;

// ---- packed f32x2 helpers (PTX-only) ----
__device__ __forceinline__ ull pack2(float lo, float hi) {
    ull r; asm("mov.b64 %0, {%1, %2};" : "=l"(r) : "f"(lo), "f"(hi)); return r;
}
__device__ __forceinline__ void unpack2(ull v, float &lo, float &hi) {
    asm("mov.b64 {%0, %1}, %2;" : "=f"(lo), "=f"(hi) : "l"(v));
}
__device__ __forceinline__ ull ffma2(ull a, ull b, ull c) {
    ull d; asm("fma.rn.f32x2 %0, %1, %2, %3;" : "=l"(d) : "l"(a), "l"(b), "l"(c)); return d;
}

// ---- MUFU.TANH activations (validated: rel_err ~2e-6) ----
__device__ __forceinline__ float tanha(float x) {
    float r; asm("tanh.approx.f32 %0, %1;" : "=f"(r) : "f"(x)); return r;
}
__device__ __forceinline__ float sigm(float x) {       // 0.5*tanh(x/2)+0.5
    return fmaf(0.5f, tanha(0.5f * x), 0.5f);
}

// ---- shared layout (bytes) ----
// wsh  : float[224][53]    47488 @ 0      W_hh rows padded (rows>=200 zero; 53 kills conflicts)
// wbsh : float2[224]        1792 @ 47488  (W_ih[g], b_ih+b_hh), zero-padded
// wlin : float[52]           208 @ 49280
// xt   : float[64][66]     16896 @ 49504
// hw   : ull[12][3][50]    14400 @ 66400  per-warp h, [pair][j] packed (b0,b1)
// zw   : ull[12][3][224]   64512 @ 80800  per-warp z scratch, [pair][gate]
#define OFF_W    0
#define OFF_WB   47488
#define OFF_WLIN 49280
#define OFF_X    49504
#define OFF_HW   66400
#define OFF_ZW   80800
#define SMEM_BYTES 145312

// one LSTM-step engine for a warp owning NP batch-pairs
template<int NP>
__device__ __forceinline__ void do_steps64(
    const float* __restrict__ xt, int wb, int l,
    ull* __restrict__ hw, ull* __restrict__ zw,
    const float* __restrict__ wsh, const float2* __restrict__ wbsh,
    float (*cst)[2])
{
    constexpr int NR = (NP * 50 + 31) / 32;   // activation rounds

    for (int ts = 0; ts < 64; ++ts) {
        const int xrow = ts * XROW;

        // ---- init accumulators: bias + W_ih * x ----
        ull acc[NP][7];
        {
            float2 xp[NP];
#pragma unroll
            for (int p = 0; p < NP; ++p)
                xp[p] = *(const float2*)&xt[xrow + wb + 2 * p];
#pragma unroll
            for (int s = 0; s < 7; ++s) {
                const float2 wbv = wbsh[l + 32 * s];
#pragma unroll
                for (int p = 0; p < NP; ++p)
                    acc[p][s] = pack2(fmaf(wbv.x, xp[p].x, wbv.y),
                                      fmaf(wbv.x, xp[p].y, wbv.y));
            }
        }

        // ---- matvec with one-j-ahead software pipeline ----
        float wvC[7]; ull hjC[NP];
#pragma unroll
        for (int s = 0; s < 7; ++s) wvC[s] = wsh[(l + 32 * s) * 53 + 0];
#pragma unroll
        for (int p = 0; p < NP; ++p) hjC[p] = hw[p * 50 + 0];

#pragma unroll 10
        for (int j = 0; j < HH; ++j) {
            const int jn = (j + 1 < HH) ? (j + 1) : 0;
            float wvN[7]; ull hjN[NP];
#pragma unroll
            for (int s = 0; s < 7; ++s) wvN[s] = wsh[(l + 32 * s) * 53 + jn];
#pragma unroll
            for (int p = 0; p < NP; ++p) hjN[p] = hw[p * 50 + jn];

#pragma unroll
            for (int s = 0; s < 7; ++s) {
                const ull w2 = pack2(wvC[s], wvC[s]);
#pragma unroll
                for (int p = 0; p < NP; ++p)
                    acc[p][s] = ffma2(w2, hjC[p], acc[p][s]);
            }
#pragma unroll
            for (int s = 0; s < 7; ++s) wvC[s] = wvN[s];
#pragma unroll
            for (int p = 0; p < NP; ++p) hjC[p] = hjN[p];
        }

        // ---- scatter z to per-warp scratch ----
#pragma unroll
        for (int s = 0; s < 7; ++s)
#pragma unroll
            for (int p = 0; p < NP; ++p)
                zw[p * 224 + l + 32 * s] = acc[p][s];
        __syncwarp();

        // ---- activations: tasks a = l + 32k over (pair, j) ----
#pragma unroll
        for (int k = 0; k < NR; ++k) {
            const int a = l + 32 * k;
            if (a < NP * 50) {
                const int p = a / 50;
                const int j = a - 50 * p;
                float zi0, zi1, zf0, zf1, zg0, zg1, zo0, zo1;
                unpack2(zw[p * 224 +       j], zi0, zi1);
                unpack2(zw[p * 224 +  50 + j], zf0, zf1);
                unpack2(zw[p * 224 + 100 + j], zg0, zg1);
                unpack2(zw[p * 224 + 150 + j], zo0, zo1);
                float h0, h1;
                {
                    const float iv = sigm(zi0), fv = sigm(zf0);
                    const float gv = tanha(zg0), ov = sigm(zo0);
                    const float c  = fmaf(fv, cst[k][0], iv * gv);
                    cst[k][0] = c;
                    h0 = ov * tanha(c);
                }
                {
                    const float iv = sigm(zi1), fv = sigm(zf1);
                    const float gv = tanha(zg1), ov = sigm(zo1);
                    const float c  = fmaf(fv, cst[k][1], iv * gv);
                    cst[k][1] = c;
                    h1 = ov * tanha(c);
                }
                hw[p * 50 + j] = pack2(h0, h1);
            }
        }
        __syncwarp();
    }
}

__global__ __launch_bounds__(NTHR, 1)
void lstm_persist_kernel(const float* __restrict__ x,
                         const float* __restrict__ W_ih,
                         const float* __restrict__ W_hh,
                         const float* __restrict__ b_ih,
                         const float* __restrict__ b_hh,
                         const float* __restrict__ W_lin,
                         const float* __restrict__ b_lin,
                         float* __restrict__ out)
{
    extern __shared__ char smem[];
    float*  wsh  = (float*)(smem + OFF_W);
    float2* wbsh = (float2*)(smem + OFF_WB);
    float*  wlin = (float*)(smem + OFF_WLIN);
    float*  xt   = (float*)(smem + OFF_X);

    const int tid = threadIdx.x;
    const int w   = tid >> 5;
    const int l   = tid & 31;

    const int np = (w < 8) ? 3 : 2;                    // pairs owned
    const int wb = (w < 8) ? 6 * w : 48 + 4 * (w - 8); // first batch (in block)

    ull* __restrict__ hw = (ull*)(smem + OFF_HW) + w * (3 * 50);
    ull* __restrict__ zw = (ull*)(smem + OFF_ZW) + w * (3 * 224);

    // ---- init shared ----
    for (int i = tid; i < 224 * 53; i += NTHR) {
        int g = i / 53, j = i - g * 53;
        wsh[i] = (g < GG && j < HH) ? W_hh[g * HH + j] : 0.0f;
    }
    for (int g = tid; g < 224; g += NTHR)
        wbsh[g] = (g < GG) ? make_float2(W_ih[g], b_ih[g] + b_hh[g])
                           : make_float2(0.0f, 0.0f);
    for (int i = tid; i < 52; i += NTHR)
        wlin[i] = (i < HH) ? W_lin[i] : 0.0f;
    for (int i = tid; i < NW * 3 * 50; i += NTHR)
        ((ull*)(smem + OFF_HW))[i] = 0ull;

    const int bbase = blockIdx.x * BPB;
    const float* __restrict__ xg = x + (size_t)bbase * TT;

    float cst[5][2];
#pragma unroll
    for (int k = 0; k < 5; ++k) { cst[k][0] = 0.0f; cst[k][1] = 0.0f; }

    __syncthreads();

    for (int t = 0; t < TT; t += 64) {
        // ---- x tile refill (uniform code; arrival-counting barrier) ----
        for (int idx = tid; idx < 64 * 64; idx += NTHR) {
            int tl = idx & 63, bb = idx >> 6;
            xt[tl * XROW + bb] = xg[(size_t)bb * TT + t + tl];
        }
        __syncthreads();

        if (np == 3) do_steps64<3>(xt, wb, l, hw, zw, wsh, wbsh, cst);
        else         do_steps64<2>(xt, wb, l, hw, zw, wsh, wbsh, cst);

        __syncthreads();   // xt reuse protection for next tile
    }

    // ---- final projection: lanes 0..2np-1 -> this warp's batches ----
    if (l < 2 * np) {
        const int p  = l >> 1;
        const int hi = l & 1;
        float s = b_lin[0];
#pragma unroll
        for (int j = 0; j < HH; ++j) {
            float h0, h1;
            unpack2(hw[p * 50 + j], h0, h1);
            s = fmaf(wlin[j], hi ? h1 : h0, s);
        }
        out[bbase + wb + l] = s;
    }
}

extern "C" void kernel_launch(void* const* d_in, const int* in_sizes, int n_in,
                              void* d_out, int out_size)
{
    const float* x     = (const float*)d_in[0];
    const float* W_ih  = (const float*)d_in[1];
    const float* W_hh  = (const float*)d_in[2];
    const float* b_ih  = (const float*)d_in[3];
    const float* b_hh  = (const float*)d_in[4];
    const float* W_lin = (const float*)d_in[5];
    const float* b_lin = (const float*)d_in[6];
    float* out = (float*)d_out;

    cudaFuncSetAttribute(lstm_persist_kernel,
                         cudaFuncAttributeMaxDynamicSharedMemorySize, SMEM_BYTES);

    lstm_persist_kernel<<<BB / BPB, NTHR, SMEM_BYTES>>>(
        x, W_ih, W_hh, b_ih, b_hh, W_lin, b_lin, out);
}

// round 15
// speedup vs baseline: 1.8044x; 1.8044x over previous
#include <cuda_runtime.h>

// Fixed problem shape
#define HH   50
#define GG   200
#define TT   2048
#define BB   8192
#define BPB  64          // batches per block
#define NW   8           // warps: each owns 8 batches (4 f32x2 pairs)
#define NTHR 256
#define XROW 66
#define WROW 60          // wsh row stride (floats); 15 16B-units, odd -> conflict-free LDS.128
#define HSTR 52          // hw stride per pair (ull); j=50,51 stay zero (quad padding)
#define ZSTR 200         // zw stride per pair (ull)

typedef unsigned long long ull;

// ---- packed f32x2 helpers (PTX-only) ----
__device__ __forceinline__ ull pack2(float lo, float hi) {
    ull r; asm("mov.b64 %0, {%1, %2};" : "=l"(r) : "f"(lo), "f"(hi)); return r;
}
__device__ __forceinline__ void unpack2(ull v, float &lo, float &hi) {
    asm("mov.b64 {%0, %1}, %2;" : "=f"(lo), "=f"(hi) : "l"(v));
}
__device__ __forceinline__ ull ffma2(ull a, ull b, ull c) {
    ull d; asm("fma.rn.f32x2 %0, %1, %2, %3;" : "=l"(d) : "l"(a), "l"(b), "l"(c)); return d;
}

// ---- MUFU.TANH activations (validated: rel_err ~2e-6) ----
__device__ __forceinline__ float tanha(float x) {
    float r; asm("tanh.approx.f32 %0, %1;" : "=f"(r) : "f"(x)); return r;
}
__device__ __forceinline__ float sigm(float x) {       // 0.5*tanh(x/2)+0.5
    return fmaf(0.5f, tanha(0.5f * x), 0.5f);
}

// ---- shared layout (bytes) ----
// wsh  : float[200][60]    48000 @ 0       W_hh rows, j-padded to 60 (50..59 zero)
// wbsh : float2[200]        1600 @ 48000   (W_ih[g], b_ih+b_hh)
// wlin : float[52]           208 @ 49600
// xt   : float[64][66]     16896 @ 49824
// hw   : ull[8][4][52]     13312 @ 66720   per-warp h, [pair][j] packed (b0,b1); j 50,51 = 0
// zw   : ull[8][4][200]    51200 @ 80032   per-warp z, [pair][gate row] packed
#define OFF_W    0
#define OFF_WB   48000
#define OFF_WLIN 49600
#define OFF_X    49824
#define OFF_HW   66720
#define OFF_ZW   80032
#define SMEM_BYTES 131232

// one 4-j quad of the matvec: rows l+32s (s=0..5), all 4 pairs
__device__ __forceinline__ void do_quad(int j0, int l,
                                        const float* __restrict__ wsh,
                                        const ull* __restrict__ hw,
                                        ull acc[4][6])
{
    float4 w4[6];
#pragma unroll
    for (int s = 0; s < 6; ++s)
        w4[s] = *(const float4*)&wsh[(l + 32 * s) * WROW + j0];
    ull h4[4][4];
#pragma unroll
    for (int p = 0; p < 4; ++p) {
        ulonglong2 a = *(const ulonglong2*)&hw[p * HSTR + j0];
        ulonglong2 b = *(const ulonglong2*)&hw[p * HSTR + j0 + 2];
        h4[p][0] = a.x; h4[p][1] = a.y; h4[p][2] = b.x; h4[p][3] = b.y;
    }
#pragma unroll
    for (int jj = 0; jj < 4; ++jj) {
#pragma unroll
        for (int s = 0; s < 6; ++s) {
            const float wv = (jj == 0) ? w4[s].x : (jj == 1) ? w4[s].y
                           : (jj == 2) ? w4[s].z : w4[s].w;
            const ull w2 = pack2(wv, wv);
#pragma unroll
            for (int p = 0; p < 4; ++p)
                acc[p][s] = ffma2(w2, h4[p][jj], acc[p][s]);
        }
    }
}

// one activation task: element (pair p, hidden j), both batches
__device__ __forceinline__ void act_one(ull* __restrict__ zw, ull* __restrict__ hw,
                                        int p, int j, float* cs)
{
    float zi0, zi1, zf0, zf1, zg0, zg1, zo0, zo1;
    unpack2(zw[p * ZSTR +       j], zi0, zi1);
    unpack2(zw[p * ZSTR +  50 + j], zf0, zf1);
    unpack2(zw[p * ZSTR + 100 + j], zg0, zg1);
    unpack2(zw[p * ZSTR + 150 + j], zo0, zo1);
    float h0, h1;
    {
        const float iv = sigm(zi0), fv = sigm(zf0);
        const float gv = tanha(zg0), ov = sigm(zo0);
        const float c  = fmaf(fv, cs[0], iv * gv);
        cs[0] = c;
        h0 = ov * tanha(c);
    }
    {
        const float iv = sigm(zi1), fv = sigm(zf1);
        const float gv = tanha(zg1), ov = sigm(zo1);
        const float c  = fmaf(fv, cs[1], iv * gv);
        cs[1] = c;
        h1 = ov * tanha(c);
    }
    hw[p * HSTR + j] = pack2(h0, h1);
}

__global__ __launch_bounds__(NTHR, 1)
void lstm_persist_kernel(const float* __restrict__ x,
                         const float* __restrict__ W_ih,
                         const float* __restrict__ W_hh,
                         const float* __restrict__ b_ih,
                         const float* __restrict__ b_hh,
                         const float* __restrict__ W_lin,
                         const float* __restrict__ b_lin,
                         float* __restrict__ out)
{
    extern __shared__ char smem[];
    float*  wsh  = (float*)(smem + OFF_W);
    float2* wbsh = (float2*)(smem + OFF_WB);
    float*  wlin = (float*)(smem + OFF_WLIN);
    float*  xt   = (float*)(smem + OFF_X);

    const int tid = threadIdx.x;
    const int w   = tid >> 5;
    const int l   = tid & 31;

    ull* __restrict__ hw = (ull*)(smem + OFF_HW) + w * (4 * HSTR);
    ull* __restrict__ zw = (ull*)(smem + OFF_ZW) + w * (4 * ZSTR);

    // ---- init shared ----
    for (int i = tid; i < GG * WROW; i += NTHR) {
        int g = i / WROW, j = i - g * WROW;
        wsh[i] = (j < HH) ? W_hh[g * HH + j] : 0.0f;
    }
    for (int g = tid; g < GG; g += NTHR)
        wbsh[g] = make_float2(W_ih[g], b_ih[g] + b_hh[g]);
    for (int i = tid; i < 52; i += NTHR)
        wlin[i] = (i < HH) ? W_lin[i] : 0.0f;
    for (int i = tid; i < NW * 4 * HSTR; i += NTHR)
        ((ull*)(smem + OFF_HW))[i] = 0ull;
    for (int i = tid; i < NW * 4 * ZSTR; i += NTHR)   // zero z -> act(-1) is a no-op
        ((ull*)(smem + OFF_ZW))[i] = 0ull;

    const int bbase = blockIdx.x * BPB;
    const float* __restrict__ xg = x + (size_t)bbase * TT;

    // precomputed activation task maps (t-invariant)
    int p1[3], j1[3], p2[3], j2[3];
#pragma unroll
    for (int k = 0; k < 3; ++k) {
        const int a = l + 32 * k;
        p1[k] = a / 24;  j1[k] = a - 24 * p1[k];          // j < 24 part
        p2[k] = a / 26;  j2[k] = 24 + (a - 26 * p2[k]);   // j >= 24 part
    }
    float c1[3][2], c2[4][2];
#pragma unroll
    for (int k = 0; k < 3; ++k) { c1[k][0] = c1[k][1] = 0.0f; }
#pragma unroll
    for (int k = 0; k < 4; ++k) { c2[k][0] = c2[k][1] = 0.0f; }

    __syncthreads();

    for (int t = 0; t < TT; ++t) {
        if ((t & 63) == 0) {
            __syncthreads();
            for (int idx = tid; idx < 64 * 64; idx += NTHR) {
                int tl = idx & 63, bb = idx >> 6;
                xt[tl * XROW + bb] = xg[(size_t)bb * TT + t + tl];
            }
            __syncthreads();
        }

        // ---- act(t-1), part 1: j < 24 (96 tasks, 3 exact rounds) ----
#pragma unroll
        for (int k = 0; k < 3; ++k) act_one(zw, hw, p1[k], j1[k], c1[k]);
        __syncwarp();

        // ---- region 2: matvec(t) quads j<24  ∥  act(t-1) part 2 (j>=24) ----
        const int xrow = (t & 63) * XROW;
        float2 xv[4];
#pragma unroll
        for (int p = 0; p < 4; ++p)
            xv[p] = *(const float2*)&xt[xrow + w * 8 + 2 * p];

        ull acc[4][6];
#pragma unroll
        for (int s = 0; s < 6; ++s) {
            const float2 wb = wbsh[l + 32 * s];
#pragma unroll
            for (int p = 0; p < 4; ++p)
                acc[p][s] = pack2(fmaf(wb.x, xv[p].x, wb.y),
                                  fmaf(wb.x, xv[p].y, wb.y));
        }

        act_one(zw, hw, p2[0], j2[0], c2[0]);
        do_quad( 0, l, wsh, hw, acc);
        do_quad( 4, l, wsh, hw, acc);
        act_one(zw, hw, p2[1], j2[1], c2[1]);
        do_quad( 8, l, wsh, hw, acc);
        do_quad(12, l, wsh, hw, acc);
        act_one(zw, hw, p2[2], j2[2], c2[2]);
        do_quad(16, l, wsh, hw, acc);
        do_quad(20, l, wsh, hw, acc);
        if (l < 8) act_one(zw, hw, 3, 42 + l, c2[3]);   // last 8 tasks of part 2
        __syncwarp();

        // ---- region 3: matvec(t) quads j>=24 + 8-row tail, then store z ----
        do_quad(24, l, wsh, hw, acc);
        do_quad(28, l, wsh, hw, acc);
        do_quad(32, l, wsh, hw, acc);
        do_quad(36, l, wsh, hw, acc);
        do_quad(40, l, wsh, hw, acc);
        do_quad(44, l, wsh, hw, acc);
        do_quad(48, l, wsh, hw, acc);

        {   // rows 192..199 (o-gate j=42..49): lane = (row, pair) combo
            const int r  = 192 + (l & 7);
            const int tp = l >> 3;
            const float2 wbr = wbsh[r];
            ull ta = pack2(fmaf(wbr.x, xv[tp].x, wbr.y),
                           fmaf(wbr.x, xv[tp].y, wbr.y));
            const float* __restrict__ wr = &wsh[r * WROW];
            const ull*   __restrict__ hp = &hw[tp * HSTR];
#pragma unroll 10
            for (int j = 0; j < HH; ++j) {
                const float wv = wr[j];
                ta = ffma2(pack2(wv, wv), hp[j], ta);
            }
            zw[tp * ZSTR + r] = ta;
        }

#pragma unroll
        for (int s = 0; s < 6; ++s)
#pragma unroll
            for (int p = 0; p < 4; ++p)
                zw[p * ZSTR + l + 32 * s] = acc[p][s];
        __syncwarp();
    }

    // ---- final act(TT-1) ----
#pragma unroll
    for (int k = 0; k < 3; ++k) act_one(zw, hw, p1[k], j1[k], c1[k]);
#pragma unroll
    for (int k = 0; k < 3; ++k) act_one(zw, hw, p2[k], j2[k], c2[k]);
    if (l < 8) act_one(zw, hw, 3, 42 + l, c2[3]);
    __syncwarp();

    // ---- final projection: lanes 0-7 -> this warp's 8 batches ----
    if (l < 8) {
        const int p  = l >> 1;
        const int hi = l & 1;
        float s = b_lin[0];
#pragma unroll
        for (int j = 0; j < HH; ++j) {
            float h0, h1;
            unpack2(hw[p * HSTR + j], h0, h1);
            s = fmaf(wlin[j], hi ? h1 : h0, s);
        }
        out[bbase + w * 8 + l] = s;
    }
}

extern "C" void kernel_launch(void* const* d_in, const int* in_sizes, int n_in,
                              void* d_out, int out_size)
{
    const float* x     = (const float*)d_in[0];
    const float* W_ih  = (const float*)d_in[1];
    const float* W_hh  = (const float*)d_in[2];
    const float* b_ih  = (const float*)d_in[3];
    const float* b_hh  = (const float*)d_in[4];
    const float* W_lin = (const float*)d_in[5];
    const float* b_lin = (const float*)d_in[6];
    float* out = (float*)d_out;

    cudaFuncSetAttribute(lstm_persist_kernel,
                         cudaFuncAttributeMaxDynamicSharedMemorySize, SMEM_BYTES);

    lstm_persist_kernel<<<BB / BPB, NTHR, SMEM_BYTES>>>(
        x, W_ih, W_hh, b_ih, b_hh, W_lin, b_lin, out);
}